// round 11
// baseline (speedup 1.0000x reference)
#include <cuda_runtime.h>

// Fixed shapes: x = (4,64,256,256) f32, stoken = 16
#define Bn 4
#define Cc 64
#define NH 16      // superpixel grid 16x16
#define NS 256     // nH*nW
#define PP 65536   // H*W

typedef unsigned long long ull;

// Scratch (allocation-free: __device__ globals)
__device__ float g_cent[Bn * NS * Cc];
__device__ float g_num [Bn * NS * Cc];
__device__ float g_den [Bn * NS];

__device__ __forceinline__ void ffma2(ull& acc, ull a, ull b) {
    asm("fma.rn.f32x2 %0, %1, %2, %0;" : "+l"(acc) : "l"(a), "l"(b));
}
__device__ __forceinline__ ull pack2(float x, float y) {
    ull r; asm("mov.b64 %0, {%1, %2};" : "=l"(r) : "f"(x), "f"(y)); return r;
}
__device__ __forceinline__ float2 unpack2(ull v) {
    float2 r; asm("mov.b64 {%0, %1}, %2;" : "=f"(r.x), "=f"(r.y) : "l"(v)); return r;
}

// ---------------------------------------------------------------------------
// Inline zero-fill of a slice [lo,hi) of plane (b,s), skipping float4s inside
// the plane's 3x3 affinity region (written by pass 1's scatter — byte-disjoint,
// no ordering needed). Fire-and-forget streaming stores.
// ---------------------------------------------------------------------------
template <int NT>
__device__ __forceinline__ void fill_slice(float4* __restrict__ A, int b, int s,
                                           int lo, int hi, int tid) {
    int si = s >> 4, sj = s & 15;
    float4* plane = A + ((size_t)(b * NS + s) << 14);   // 16384 float4 per plane
    const float4 z = make_float4(0.f, 0.f, 0.f, 0.f);
    #pragma unroll 4
    for (int e4 = lo + tid; e4 < hi; e4 += NT) {
        int p = e4 << 2;
        int bi = p >> 12;
        int bj = (p >> 4) & 15;
        int di = si - bi + 1, dj = sj - bj + 1;
        if ((unsigned)di > 2u || (unsigned)dj > 2u)
            __stcs(&plane[e4], z);
    }
}

#define FILL_INIT_END 3584
#define FILL_P0_END   8192

// ---------------------------------------------------------------------------
// Initial centroids: block mean over each 16x16 block. Also zeroes scratch
// and fills its plane slice [0, FILL_INIT_END).  (unchanged from r6)
// ---------------------------------------------------------------------------
__global__ __launch_bounds__(256) void init_cent_kernel(const float* __restrict__ x,
                                                        float4* __restrict__ A) {
    int b = blockIdx.y, s = blockIdx.x;
    int bi = s >> 4, bj = s & 15;
    int tid = threadIdx.x;

    fill_slice<256>(A, b, s, 0, FILL_INIT_END, tid);

    int c = tid >> 2, q = tid & 3;
    int base = ((bi * 16) << 8) + bj * 16;
    const float4* fc = (const float4*)(x + (((size_t)b * Cc + c) << 16) + base);
    float4 s4 = make_float4(0.f, 0.f, 0.f, 0.f);
    #pragma unroll 4
    for (int t = 0; t < 16; t++) {
        int j = q + t * 4;
        float4 v = fc[(j >> 2) * 64 + (j & 3)];
        s4.x += v.x; s4.y += v.y; s4.z += v.z; s4.w += v.w;
    }
    float acc = (s4.x + s4.y) + (s4.z + s4.w);
    __shared__ float part[256];
    part[tid] = acc;
    __syncthreads();
    if (tid < 64) {
        int o4 = tid * 4;
        float v = (part[o4] + part[o4 + 1]) + (part[o4 + 2] + part[o4 + 3]);
        int idx = (b * NS + s) * Cc + tid;
        g_cent[idx] = v * (1.f / 256.f);
        g_num[idx]  = 0.f;
    }
    if (tid == 64) g_den[b * NS + s] = 0.f;
}

// ---------------------------------------------------------------------------
// Affinity pass. CTA = 64 threads = one 16x16 block; each thread owns 4
// horizontally-adjacent pixels -> all x reads are LDG.128 on the pixel axis.
// f32x2 math on pixel pairs; centroids staged duplicated (-2*cent in both
// halves) so the inner loop is 1 LDS.64 + 2 FFMA2 per (k,channel).
//   dist = f2 + 0.25*sum(t^2) + sum(f*t),  t = -2*cent
// ---------------------------------------------------------------------------
template <int PASS>
__global__ __launch_bounds__(64) void affinity_kernel(const float* __restrict__ x,
                                                      float* __restrict__ A) {
    int b = blockIdx.y, sblk = blockIdx.x;
    int bi = sblk >> 4, bj = sblk & 15;
    int tid = threadIdx.x;

    __shared__ ull   cent2_sm[9][64];       // -2*cent duplicated in both halves
    __shared__ float c2_sm[9];
    __shared__ float den_sm[9];
    __shared__ int   cand_s[9];
    __shared__ int   cand_v[9];
    __shared__ __align__(16) float aff_sm[9][256];   // pass0 only
    __shared__ float denpart[2][9];

    if (tid < 9) {
        int ci = bi + tid / 3 - 1, cj = bj + tid % 3 - 1;
        int v = (ci >= 0 && ci < NH && cj >= 0 && cj < NH);
        cand_v[tid] = v;
        int s = v ? ci * NH + cj : 0;
        cand_s[tid] = s;
        if (PASS == 1) den_sm[tid] = g_den[b * NS + s] + 1e-16f;
    }

    // streamed zero-fill of this CTA's plane slice (overlaps with compute)
    if (PASS == 0) fill_slice<64>((float4*)A, b, sblk, FILL_INIT_END, FILL_P0_END, tid);
    else           fill_slice<64>((float4*)A, b, sblk, FILL_P0_END, 16384, tid);

    __syncthreads();
    #pragma unroll
    for (int k = 0; k < 9; k++) {
        int gi = (b * NS + cand_s[k]) * Cc + tid;
        float cv = (PASS == 0) ? g_cent[gi] : g_num[gi] / den_sm[k];
        float t2 = -2.f * cv;
        cent2_sm[k][tid] = pack2(t2, t2);
    }
    __syncthreads();
    if (tid < 9) {
        float s2 = 0.f;
        #pragma unroll 8
        for (int c = 0; c < 64; c++) {
            float2 h = unpack2(cent2_sm[tid][c]);
            s2 += h.x * h.x;
        }
        c2_sm[tid] = 0.25f * s2;
    }
    __syncthreads();

    // ---- dot phase: 4 pixels/thread, LDG.128 per channel ----
    int row = tid >> 2, cq = (tid & 3) << 2;
    int p0 = ((bi * 16 + row) << 8) + bj * 16 + cq;       // first of 4 pixels
    const float* fb = x + (((size_t)b * Cc) << 16) + p0;
    ull d01[9], d23[9];
    #pragma unroll
    for (int k = 0; k < 9; k++) { d01[k] = 0ull; d23[k] = 0ull; }
    ull f01 = 0ull, f23 = 0ull;
    #pragma unroll 4
    for (int c = 0; c < 64; c++) {
        float4 fq = __ldg((const float4*)(fb + ((size_t)c << 16)));
        ull u01 = pack2(fq.x, fq.y), u23 = pack2(fq.z, fq.w);
        ffma2(f01, u01, u01);
        ffma2(f23, u23, u23);
        #pragma unroll
        for (int k = 0; k < 9; k++) {
            ull cv = cent2_sm[k][c];
            ffma2(d01[k], u01, cv);
            ffma2(d23[k], u23, cv);
        }
    }
    float2 s01 = unpack2(f01), s23 = unpack2(f23);

    // ---- per-pixel masked softmax over 9 candidates ----
    float a0[9], a1[9], a2[9], a3[9];
    #pragma unroll
    for (int k = 0; k < 9; k++) {
        float2 e01 = unpack2(d01[k]), e23 = unpack2(d23[k]);
        float cb = c2_sm[k];
        bool v = cand_v[k] != 0;
        a0[k] = v ? -(s01.x + cb + e01.x) : -1e30f;
        a1[k] = v ? -(s01.y + cb + e01.y) : -1e30f;
        a2[k] = v ? -(s23.x + cb + e23.x) : -1e30f;
        a3[k] = v ? -(s23.y + cb + e23.y) : -1e30f;
    }
    #define SOFTMAX9(a) do {                                            \
        float mx = -3.0e38f;                                            \
        _Pragma("unroll") for (int k = 0; k < 9; k++) mx = fmaxf(mx, a[k]); \
        float ss = 0.f;                                                 \
        _Pragma("unroll") for (int k = 0; k < 9; k++) { a[k] = __expf(a[k] - mx); ss += a[k]; } \
        float rs = 1.f / ss;                                            \
        _Pragma("unroll") for (int k = 0; k < 9; k++) a[k] *= rs;       \
    } while (0)
    SOFTMAX9(a0); SOFTMAX9(a1); SOFTMAX9(a2); SOFTMAX9(a3);
    #pragma unroll
    for (int k = 0; k < 9; k++) {
        if (!cand_v[k]) { a0[k] = 0.f; a1[k] = 0.f; a2[k] = 0.f; a3[k] = 0.f; }
    }

    if (PASS == 0) {
        // stash affinities (local pixel quad = tid*4) + den partials
        float ds[9];
        #pragma unroll
        for (int k = 0; k < 9; k++) {
            *(float4*)&aff_sm[k][tid * 4] = make_float4(a0[k], a1[k], a2[k], a3[k]);
            ds[k] = (a0[k] + a1[k]) + (a2[k] + a3[k]);
        }
        #pragma unroll
        for (int k = 0; k < 9; k++) {
            float v = ds[k];
            v += __shfl_xor_sync(0xffffffffu, v, 16);
            v += __shfl_xor_sync(0xffffffffu, v, 8);
            v += __shfl_xor_sync(0xffffffffu, v, 4);
            v += __shfl_xor_sync(0xffffffffu, v, 2);
            v += __shfl_xor_sync(0xffffffffu, v, 1);
            if ((tid & 31) == 0) denpart[tid >> 5][k] = v;
        }
        __syncthreads();

        // num[k][c]: thread = channel c; pixel-quad LDG.128 (L1-hot) x bcast LDS
        int c = tid;
        const float* fc = x + (((size_t)(b * Cc + c)) << 16);
        int base = ((bi * 16) << 8) + bj * 16;
        ull acc[9];
        #pragma unroll
        for (int k = 0; k < 9; k++) acc[k] = 0ull;
        #pragma unroll 4
        for (int q = 0; q < 64; q++) {
            int r = q >> 2, c4 = (q & 3) << 2;
            float4 fq = __ldg((const float4*)(fc + base + (r << 8) + c4));
            ull u01 = pack2(fq.x, fq.y), u23 = pack2(fq.z, fq.w);
            #pragma unroll
            for (int k = 0; k < 9; k++) {
                const ull* ap = (const ull*)&aff_sm[k][0];
                ffma2(acc[k], u01, ap[q * 2]);
                ffma2(acc[k], u23, ap[q * 2 + 1]);
            }
        }
        #pragma unroll
        for (int k = 0; k < 9; k++) {
            if (cand_v[k]) {
                float2 h = unpack2(acc[k]);
                atomicAdd(&g_num[(b * NS + cand_s[k]) * Cc + c], h.x + h.y);
            }
        }
        if (tid < 9 && cand_v[tid])
            atomicAdd(&g_den[b * NS + cand_s[tid]], denpart[0][tid] + denpart[1][tid]);
    } else {
        // scatter: pixel quad = one float4 per candidate, straight from regs
        #pragma unroll
        for (int k = 0; k < 9; k++) {
            if (cand_v[k]) {
                size_t off = (((size_t)(b * NS + cand_s[k])) << 16) + p0;
                __stcs((float4*)(A + off), make_float4(a0[k], a1[k], a2[k], a3[k]));
            }
        }
    }
}

extern "C" void kernel_launch(void* const* d_in, const int* in_sizes, int n_in,
                              void* d_out, int out_size) {
    const float* x = (const float*)d_in[0];
    float* A = (float*)d_out;

    dim3 grid(NS, Bn);
    init_cent_kernel<<<grid, 256>>>(x, (float4*)A);
    affinity_kernel<0><<<grid, 64>>>(x, A);
    affinity_kernel<1><<<grid, 64>>>(x, A);
}

// round 12
// speedup vs baseline: 1.1213x; 1.1213x over previous
#include <cuda_runtime.h>

// Fixed shapes: x = (4,64,256,256) f32, stoken = 16
#define Bn 4
#define Cc 64
#define NH 16      // superpixel grid 16x16
#define NS 256     // nH*nW
#define PP 65536   // H*W

typedef unsigned long long ull;

// Scratch (allocation-free: __device__ globals)
__device__ float g_cent[Bn * NS * Cc];
__device__ float g_num [Bn * NS * Cc];
__device__ float g_den [Bn * NS];

__device__ __forceinline__ void ffma2(ull& acc, ull a, ull b) {
    asm("fma.rn.f32x2 %0, %1, %2, %0;" : "+l"(acc) : "l"(a), "l"(b));
}
__device__ __forceinline__ ull pack2(float x, float y) {
    ull r; asm("mov.b64 %0, {%1, %2};" : "=l"(r) : "f"(x), "f"(y)); return r;
}
__device__ __forceinline__ float2 unpack2(ull v) {
    float2 r; asm("mov.b64 {%0, %1}, %2;" : "=f"(r.x), "=f"(r.y) : "l"(v)); return r;
}

// ---------------------------------------------------------------------------
// Inline zero-fill of a slice [lo,hi) of plane (b,s), skipping float4s inside
// the plane's 3x3 affinity region (written by pass 1's scatter — byte-disjoint,
// no ordering needed). Fire-and-forget streaming stores that drain while the
// caller's compute stalls on load latency.
// ---------------------------------------------------------------------------
__device__ __forceinline__ void fill_slice(float4* __restrict__ A, int b, int s,
                                           int lo, int hi, int tid) {
    int si = s >> 4, sj = s & 15;
    float4* plane = A + ((size_t)(b * NS + s) << 14);   // 16384 float4 per plane
    const float4 z = make_float4(0.f, 0.f, 0.f, 0.f);
    #pragma unroll 4
    for (int e4 = lo + tid; e4 < hi; e4 += 256) {
        int p = e4 << 2;
        int bi = p >> 12;
        int bj = (p >> 4) & 15;
        int di = si - bi + 1, dj = sj - bj + 1;
        if ((unsigned)di > 2u || (unsigned)dj > 2u)
            __stcs(&plane[e4], z);
    }
}

// Fill split across the three chain kernels (16384 float4 per plane total).
#define FILL_INIT_END 3584
#define FILL_P0_END   9984

// ---------------------------------------------------------------------------
// Initial centroids: block mean over each 16x16 block. Also zeroes scratch
// and fills its plane slice [0, FILL_INIT_END).
// ---------------------------------------------------------------------------
__global__ __launch_bounds__(256) void init_cent_kernel(const float* __restrict__ x,
                                                        float4* __restrict__ A) {
    int b = blockIdx.y, s = blockIdx.x;
    int bi = s >> 4, bj = s & 15;
    int tid = threadIdx.x;

    fill_slice(A, b, s, 0, FILL_INIT_END, tid);

    int c = tid >> 2, q = tid & 3;
    int base = ((bi * 16) << 8) + bj * 16;
    const float4* fc = (const float4*)(x + (((size_t)b * Cc + c) << 16) + base);
    float4 s4 = make_float4(0.f, 0.f, 0.f, 0.f);
    #pragma unroll
    for (int t = 0; t < 16; t++) {
        int j = q + t * 4;                 // float4 index within block
        float4 v = fc[(j >> 2) * 64 + (j & 3)];
        s4.x += v.x; s4.y += v.y; s4.z += v.z; s4.w += v.w;
    }
    float acc = (s4.x + s4.y) + (s4.z + s4.w);
    __shared__ float part[256];
    part[tid] = acc;
    __syncthreads();
    if (tid < 64) {
        int o4 = tid * 4;
        float v = (part[o4] + part[o4 + 1]) + (part[o4 + 2] + part[o4 + 3]);
        int idx = (b * NS + s) * Cc + tid;
        g_cent[idx] = v * (1.f / 256.f);
        g_num[idx]  = 0.f;
    }
    if (tid == 64) g_den[b * NS + s] = 0.f;
}

// ---------------------------------------------------------------------------
// Affinity pass. One CTA per (b, 16x16 pixel block); 256 threads = 256 pixels.
// cent_sm holds t = -2*cent. Softmax is invariant to the per-pixel f2 shift,
// so logits are just -(0.25*sum(t^2) + sum(f*t)) = -(c2 - 2*dot): the f2
// self-dot is never computed.
// PASS 0: centroids from g_cent; fused num/den reduction; fills middle slice.
// PASS 1: centroids from g_num/g_den; scatters into A; fills last slice.
// ---------------------------------------------------------------------------
template <int PASS>
__global__ __launch_bounds__(256) void affinity_kernel(const float* __restrict__ x,
                                                       float* __restrict__ A) {
    int b = blockIdx.y, sblk = blockIdx.x;
    int bi = sblk >> 4, bj = sblk & 15;
    int tid = threadIdx.x;

    __shared__ __align__(16) float cent_sm[9][64];   // -2 * centroid
    __shared__ __align__(16) float aff_sm[9][256];
    __shared__ float c2_sm[9];
    __shared__ float den_sm[9];
    __shared__ int   cand_s[9];
    __shared__ int   cand_v[9];

    if (tid < 9) {
        int ci = bi + tid / 3 - 1, cj = bj + tid % 3 - 1;
        int v = (ci >= 0 && ci < NH && cj >= 0 && cj < NH);
        cand_v[tid] = v;
        int s = v ? ci * NH + cj : 0;
        cand_s[tid] = s;
        if (PASS == 1) den_sm[tid] = g_den[b * NS + s] + 1e-16f;
    }

    // streamed zero-fill of this CTA's plane slice (overlaps with compute)
    if (PASS == 0) fill_slice((float4*)A, b, sblk, FILL_INIT_END, FILL_P0_END, tid);
    else           fill_slice((float4*)A, b, sblk, FILL_P0_END, 16384, tid);

    __syncthreads();
    for (int i = tid; i < 9 * 64; i += 256) {
        int k = i >> 6, c = i & 63;
        int gi = (b * NS + cand_s[k]) * Cc + c;
        float cv = (PASS == 0) ? g_cent[gi] : g_num[gi] / den_sm[k];
        cent_sm[k][c] = -2.f * cv;
    }
    __syncthreads();
    if (tid < 9) {
        float s2 = 0.f;
        #pragma unroll 8
        for (int c = 0; c < 64; c++) { float v = cent_sm[tid][c]; s2 += v * v; }
        c2_sm[tid] = 0.25f * s2;          // sum(cent^2)
    }
    __syncthreads();

    // ---- per-pixel dots: 8-wide LDG batches (2x in-flight bytes vs r6) ----
    int ly = tid >> 4, lx = tid & 15;
    int p = ((bi * 16 + ly) << 8) + bj * 16 + lx;
    const float* fb = x + (((size_t)b * Cc) << 16) + p;
    ull dacc[9];
    #pragma unroll
    for (int k = 0; k < 9; k++) dacc[k] = 0ull;
    #pragma unroll
    for (int cc = 0; cc < 64; cc += 8) {
        float f[8];
        #pragma unroll
        for (int j = 0; j < 8; j++) f[j] = fb[(size_t)(cc + j) << 16];
        #pragma unroll
        for (int q = 0; q < 8; q += 4) {
            ull fp0 = pack2(f[q], f[q + 1]), fp1 = pack2(f[q + 2], f[q + 3]);
            #pragma unroll
            for (int k = 0; k < 9; k++) {
                float4 cv = *(const float4*)&cent_sm[k][cc + q];
                ffma2(dacc[k], fp0, pack2(cv.x, cv.y));
                ffma2(dacc[k], fp1, pack2(cv.z, cv.w));
            }
        }
    }

    // ---- masked softmax over 9 candidates (f2 shift dropped) ----
    float aff[9];
    float mx = -3.0e38f;
    #pragma unroll
    for (int k = 0; k < 9; k++) {
        float2 dh = unpack2(dacc[k]);
        float d = c2_sm[k] + (dh.x + dh.y);
        aff[k] = cand_v[k] ? -d : -1e30f;
        mx = fmaxf(mx, aff[k]);
    }
    float ssum = 0.f;
    #pragma unroll
    for (int k = 0; k < 9; k++) { float e = __expf(aff[k] - mx); aff[k] = e; ssum += e; }
    float rs = 1.f / ssum;
    #pragma unroll
    for (int k = 0; k < 9; k++) aff[k] = cand_v[k] ? aff[k] * rs : 0.f;

    #pragma unroll
    for (int k = 0; k < 9; k++) aff_sm[k][tid] = aff[k];

    if (PASS == 0) {
        // den: warp reduce each of 9 affinities over the 256 pixels
        __shared__ float denpart[8][9];
        #pragma unroll
        for (int k = 0; k < 9; k++) {
            float v = aff[k];
            v += __shfl_xor_sync(0xffffffffu, v, 16);
            v += __shfl_xor_sync(0xffffffffu, v, 8);
            v += __shfl_xor_sync(0xffffffffu, v, 4);
            v += __shfl_xor_sync(0xffffffffu, v, 2);
            v += __shfl_xor_sync(0xffffffffu, v, 1);
            if ((tid & 31) == 0) denpart[tid >> 5][k] = v;
        }
        __syncthreads();

        // num[k][c] = sum_p aff[k][p] * feats[c][p]  (pixel-quad, LDG.128)
        int c = tid >> 2, g = tid & 3;
        const float* fc = x + (((size_t)b * Cc + c) << 16);
        int base = ((bi * 16) << 8) + bj * 16;
        ull acc2[9];
        #pragma unroll
        for (int k = 0; k < 9; k++) acc2[k] = 0ull;
        #pragma unroll 4
        for (int t = 0; t < 16; t++) {
            int j = g + t * 4;                        // pixel-quad index [0,64)
            int row = j >> 2, c4 = j & 3;
            int i = row * 16 + c4 * 4;                // local pixel base
            float4 fq = *(const float4*)(fc + base + (row << 8) + c4 * 4);
            ull fp0 = pack2(fq.x, fq.y), fp1 = pack2(fq.z, fq.w);
            #pragma unroll
            for (int k = 0; k < 9; k++) {
                float4 aq = *(const float4*)&aff_sm[k][i];
                ffma2(acc2[k], fp0, pack2(aq.x, aq.y));
                ffma2(acc2[k], fp1, pack2(aq.z, aq.w));
            }
        }
        __shared__ float part[9][256];
        #pragma unroll
        for (int k = 0; k < 9; k++) {
            float2 h = unpack2(acc2[k]);
            part[k][tid] = h.x + h.y;
        }
        __syncthreads();

        for (int i = tid; i < 9 * 64; i += 256) {
            int k = i >> 6, c2i = i & 63;
            if (cand_v[k]) {
                int o4 = c2i * 4;
                float v = (part[k][o4] + part[k][o4 + 1]) + (part[k][o4 + 2] + part[k][o4 + 3]);
                atomicAdd(&g_num[(b * NS + cand_s[k]) * Cc + c2i], v);
            }
        }
        if (tid < 9 && cand_v[tid]) {
            float v = 0.f;
            #pragma unroll
            for (int w = 0; w < 8; w++) v += denpart[w][tid];
            atomicAdd(&g_den[b * NS + cand_s[tid]], v);
        }
    } else {
        // scatter into dense A with vectorized streaming stores
        __syncthreads();
        for (int i = tid; i < 9 * 64; i += 256) {
            int k = i >> 6, e4 = i & 63;
            if (cand_v[k]) {
                int row = e4 >> 2, c4 = e4 & 3;
                float4 v = *(const float4*)&aff_sm[k][row * 16 + c4 * 4];
                size_t off = (((size_t)(b * NS + cand_s[k])) << 16)
                           + (((bi * 16 + row) << 8) + bj * 16 + c4 * 4);
                __stcs((float4*)(A + off), v);
            }
        }
    }
}

extern "C" void kernel_launch(void* const* d_in, const int* in_sizes, int n_in,
                              void* d_out, int out_size) {
    const float* x = (const float*)d_in[0];
    float* A = (float*)d_out;

    dim3 grid(NS, Bn);
    // Single stream; zero-fill is folded into each kernel as streaming stores.
    init_cent_kernel<<<grid, 256>>>(x, (float4*)A);
    affinity_kernel<0><<<grid, 256>>>(x, A);
    affinity_kernel<1><<<grid, 256>>>(x, A);
}

// round 13
// speedup vs baseline: 1.1938x; 1.0646x over previous
#include <cuda_runtime.h>

// Fixed shapes: x = (4,64,256,256) f32, stoken = 16
#define Bn 4
#define Cc 64
#define NH 16      // superpixel grid 16x16
#define NS 256     // nH*nW
#define PP 65536   // H*W

typedef unsigned long long ull;

// Scratch (allocation-free: __device__ globals)
__device__ float g_cent[Bn * NS * Cc];
__device__ float g_num [Bn * NS * Cc];
__device__ float g_den [Bn * NS];

__device__ __forceinline__ void ffma2(ull& acc, ull a, ull b) {
    asm("fma.rn.f32x2 %0, %1, %2, %0;" : "+l"(acc) : "l"(a), "l"(b));
}
__device__ __forceinline__ ull pack2(float x, float y) {
    ull r; asm("mov.b64 %0, {%1, %2};" : "=l"(r) : "f"(x), "f"(y)); return r;
}
__device__ __forceinline__ float2 unpack2(ull v) {
    float2 r; asm("mov.b64 {%0, %1}, %2;" : "=f"(r.x), "=f"(r.y) : "l"(v)); return r;
}

// ---------------------------------------------------------------------------
// Inline zero-fill of a slice [lo,hi) of plane (b,s), skipping float4s inside
// the plane's 3x3 affinity region (written by pass 1's scatter — byte-disjoint,
// no ordering needed). Fire-and-forget streaming stores.
// ---------------------------------------------------------------------------
template <int NT>
__device__ __forceinline__ void fill_slice(float4* __restrict__ A, int b, int s,
                                           int lo, int hi, int tid) {
    int si = s >> 4, sj = s & 15;
    float4* plane = A + ((size_t)(b * NS + s) << 14);   // 16384 float4 per plane
    const float4 z = make_float4(0.f, 0.f, 0.f, 0.f);
    #pragma unroll 4
    for (int e4 = lo + tid; e4 < hi; e4 += NT) {
        int p = e4 << 2;
        int bi = p >> 12;
        int bj = (p >> 4) & 15;
        int di = si - bi + 1, dj = sj - bj + 1;
        if ((unsigned)di > 2u || (unsigned)dj > 2u)
            __stcs(&plane[e4], z);
    }
}

// Fill split across the three chain kernels (16384 float4 per plane total).
#define FILL_INIT_END 3584
#define FILL_P0_END   9984

// ---------------------------------------------------------------------------
// Initial centroids: block mean over each 16x16 block. Also zeroes scratch
// and fills its plane slice [0, FILL_INIT_END).  (unchanged from r12)
// ---------------------------------------------------------------------------
__global__ __launch_bounds__(256) void init_cent_kernel(const float* __restrict__ x,
                                                        float4* __restrict__ A) {
    int b = blockIdx.y, s = blockIdx.x;
    int bi = s >> 4, bj = s & 15;
    int tid = threadIdx.x;

    fill_slice<256>(A, b, s, 0, FILL_INIT_END, tid);

    int c = tid >> 2, q = tid & 3;
    int base = ((bi * 16) << 8) + bj * 16;
    const float4* fc = (const float4*)(x + (((size_t)b * Cc + c) << 16) + base);
    float4 s4 = make_float4(0.f, 0.f, 0.f, 0.f);
    #pragma unroll
    for (int t = 0; t < 16; t++) {
        int j = q + t * 4;
        float4 v = fc[(j >> 2) * 64 + (j & 3)];
        s4.x += v.x; s4.y += v.y; s4.z += v.z; s4.w += v.w;
    }
    float acc = (s4.x + s4.y) + (s4.z + s4.w);
    __shared__ float part[256];
    part[tid] = acc;
    __syncthreads();
    if (tid < 64) {
        int o4 = tid * 4;
        float v = (part[o4] + part[o4 + 1]) + (part[o4 + 2] + part[o4 + 3]);
        int idx = (b * NS + s) * Cc + tid;
        g_cent[idx] = v * (1.f / 256.f);
        g_num[idx]  = 0.f;
    }
    if (tid == 64) g_den[b * NS + s] = 0.f;
}

// ---------------------------------------------------------------------------
// Affinity pass. CTA = 128 threads = one 16x16 block; each thread owns 2
// ADJACENT pixels, so all x accesses are LDG.64 and all f32x2 accumulators
// carry (pixel0, pixel1) — zero pack overhead. Centroids staged duplicated:
// cent2_sm[k][c] = (-2*cent, -2*cent). Softmax shift-invariance drops f2:
// logit = -(0.25*sum(t^2) + sum(f*t)).
// PASS 0: fused num/den reduction (pair loads + partner-shuffle atomics).
// PASS 1: direct STG.64 scatter from registers.
// ---------------------------------------------------------------------------
template <int PASS>
__global__ __launch_bounds__(128) void affinity_kernel(const float* __restrict__ x,
                                                       float* __restrict__ A) {
    int b = blockIdx.y, sblk = blockIdx.x;
    int bi = sblk >> 4, bj = sblk & 15;
    int tid = threadIdx.x;

    __shared__ __align__(16) ull cent2_sm[9][64];   // (-2c, -2c) per channel
    __shared__ ull   aff_sm[9][128];                // pair-packed (pass0 only)
    __shared__ float c2_sm[9];
    __shared__ float den_sm[9];
    __shared__ int   cand_s[9];
    __shared__ int   cand_v[9];
    __shared__ float denpart[4][9];

    if (tid < 9) {
        int ci = bi + tid / 3 - 1, cj = bj + tid % 3 - 1;
        int v = (ci >= 0 && ci < NH && cj >= 0 && cj < NH);
        cand_v[tid] = v;
        int s = v ? ci * NH + cj : 0;
        cand_s[tid] = s;
        if (PASS == 1) den_sm[tid] = g_den[b * NS + s] + 1e-16f;
    }

    // streamed zero-fill of this CTA's plane slice (overlaps with compute)
    if (PASS == 0) fill_slice<128>((float4*)A, b, sblk, FILL_INIT_END, FILL_P0_END, tid);
    else           fill_slice<128>((float4*)A, b, sblk, FILL_P0_END, 16384, tid);

    __syncthreads();
    for (int i = tid; i < 9 * 64; i += 128) {
        int k = i >> 6, c = i & 63;
        int gi = (b * NS + cand_s[k]) * Cc + c;
        float cv = (PASS == 0) ? g_cent[gi] : g_num[gi] / den_sm[k];
        float t2 = -2.f * cv;
        cent2_sm[k][c] = pack2(t2, t2);
    }
    __syncthreads();
    if (tid < 9) {
        float s2 = 0.f;
        #pragma unroll 8
        for (int c = 0; c < 64; c++) {
            float2 h = unpack2(cent2_sm[tid][c]);
            s2 += h.x * h.x;
        }
        c2_sm[tid] = 0.25f * s2;
    }
    __syncthreads();

    // ---- dot phase: pixel pair per thread, 8-channel LDG.64 batches ----
    int row = tid >> 3, cp = tid & 7;
    int p0 = ((bi * 16 + row) << 8) + bj * 16 + (cp << 1);   // first of pair
    const float* fb = x + (((size_t)b * Cc) << 16) + p0;
    ull dacc[9];
    #pragma unroll
    for (int k = 0; k < 9; k++) dacc[k] = 0ull;
    #pragma unroll
    for (int cc = 0; cc < 64; cc += 8) {
        ull f[8];
        #pragma unroll
        for (int j = 0; j < 8; j++)
            f[j] = *(const ull*)(fb + ((size_t)(cc + j) << 16));
        #pragma unroll
        for (int j = 0; j < 8; j += 2) {
            #pragma unroll
            for (int k = 0; k < 9; k++) {
                ulonglong2 cv = *(const ulonglong2*)&cent2_sm[k][cc + j];
                ffma2(dacc[k], f[j],     cv.x);
                ffma2(dacc[k], f[j + 1], cv.y);
            }
        }
    }

    // ---- masked softmax for both pixels ----
    float a0[9], a1[9];
    #pragma unroll
    for (int k = 0; k < 9; k++) {
        float2 dh = unpack2(dacc[k]);
        float cb = c2_sm[k];
        bool v = cand_v[k] != 0;
        a0[k] = v ? -(cb + dh.x) : -1e30f;
        a1[k] = v ? -(cb + dh.y) : -1e30f;
    }
    #define SOFTMAX9(a) do {                                                \
        float mx = -3.0e38f;                                                \
        _Pragma("unroll") for (int k = 0; k < 9; k++) mx = fmaxf(mx, a[k]); \
        float ss = 0.f;                                                     \
        _Pragma("unroll") for (int k = 0; k < 9; k++) { a[k] = __expf(a[k] - mx); ss += a[k]; } \
        float rs = 1.f / ss;                                                \
        _Pragma("unroll") for (int k = 0; k < 9; k++) a[k] *= rs;           \
    } while (0)
    SOFTMAX9(a0); SOFTMAX9(a1);
    #pragma unroll
    for (int k = 0; k < 9; k++)
        if (!cand_v[k]) { a0[k] = 0.f; a1[k] = 0.f; }

    if (PASS == 0) {
        // stash pair-packed affinities + den warp partials
        float ds[9];
        #pragma unroll
        for (int k = 0; k < 9; k++) {
            aff_sm[k][tid] = pack2(a0[k], a1[k]);
            ds[k] = a0[k] + a1[k];
        }
        #pragma unroll
        for (int k = 0; k < 9; k++) {
            float v = ds[k];
            v += __shfl_xor_sync(0xffffffffu, v, 16);
            v += __shfl_xor_sync(0xffffffffu, v, 8);
            v += __shfl_xor_sync(0xffffffffu, v, 4);
            v += __shfl_xor_sync(0xffffffffu, v, 2);
            v += __shfl_xor_sync(0xffffffffu, v, 1);
            if ((tid & 31) == 0) denpart[tid >> 5][k] = v;
        }
        __syncthreads();

        // num[k][c] = sum_p aff[k][p]*x[c][p]: thread = (channel, half)
        int c = tid >> 1, g = tid & 1;
        const float* fc = x + (((size_t)(b * Cc + c)) << 16);
        int base = ((bi * 16) << 8) + bj * 16;
        ull acc[9];
        #pragma unroll
        for (int k = 0; k < 9; k++) acc[k] = 0ull;
        #pragma unroll 4
        for (int t = 0; t < 64; t++) {
            int q = t * 2 + g;                         // pair index 0..127
            int r = q >> 3, cpq = q & 7;
            ull fp = *(const ull*)(fc + base + (r << 8) + (cpq << 1));
            #pragma unroll
            for (int k = 0; k < 9; k++)
                ffma2(acc[k], fp, aff_sm[k][q]);
        }
        #pragma unroll
        for (int k = 0; k < 9; k++) {
            float2 h = unpack2(acc[k]);
            float v = h.x + h.y;
            v += __shfl_xor_sync(0xffffffffu, v, 1);   // partner (g=0/1) merge
            if (g == 0 && cand_v[k])
                atomicAdd(&g_num[(b * NS + cand_s[k]) * Cc + c], v);
        }
        if (tid < 9 && cand_v[tid]) {
            float v = (denpart[0][tid] + denpart[1][tid])
                    + (denpart[2][tid] + denpart[3][tid]);
            atomicAdd(&g_den[b * NS + cand_s[tid]], v);
        }
    } else {
        // scatter: pixel pair = one STG.64 per candidate, straight from regs
        #pragma unroll
        for (int k = 0; k < 9; k++) {
            if (cand_v[k]) {
                size_t off = (((size_t)(b * NS + cand_s[k])) << 16) + p0;
                __stcs((float2*)(A + off), make_float2(a0[k], a1[k]));
            }
        }
    }
}

extern "C" void kernel_launch(void* const* d_in, const int* in_sizes, int n_in,
                              void* d_out, int out_size) {
    const float* x = (const float*)d_in[0];
    float* A = (float*)d_out;

    dim3 grid(NS, Bn);
    // Single stream; zero-fill is folded into each kernel as streaming stores.
    init_cent_kernel<<<grid, 256>>>(x, (float4*)A);
    affinity_kernel<0><<<grid, 128>>>(x, A);
    affinity_kernel<1><<<grid, 128>>>(x, A);
}